// round 5
// baseline (speedup 1.0000x reference)
#include <cuda_runtime.h>
#include <math.h>

typedef unsigned long long ull;

#define Bz 32
#define Sz 512
#define Ez 256
#define Uz 1024
#define U2 2048
#define BSz (Bz*Sz)   // 16384

#define NBLK 128
#define NTHR 512
#define NGRP 16        // 16 groups of 8 blocks

// -------- scratch (device globals; no allocation allowed) --------
__device__ float g_Xg[(size_t)BSz * U2];
__device__ float g_Xc[(size_t)BSz * Uz];
__device__ float g_y0[(size_t)BSz * Uz];
__device__ float g_h [Bz * Uz];
__device__ float g_u [Bz * Uz];
__device__ float g_a [Bz * Uz];

// -------- two-level grid barrier state (all zero-init) --------
__device__ unsigned g_cnt[NGRP * 32];    // group arrive counters, 128B apart
__device__ unsigned g_rootc;             // root arrive counter
__device__ unsigned g_flag[NGRP * 32];   // per-group release flags, 128B apart

// -------- f32x2 packed-math helpers (pack axis = k) --------
__device__ __forceinline__ void fma2(ull& d, ull a, ull b) {
    asm("fma.rn.f32x2 %0, %1, %2, %0;" : "+l"(d) : "l"(a), "l"(b));
}
__device__ __forceinline__ void add2(ull& d, ull a) {
    asm("add.rn.f32x2 %0, %1, %0;" : "+l"(d) : "l"(a));
}
__device__ __forceinline__ float hadd2(ull v) {
    float2 r; asm("mov.b64 {%0,%1}, %2;" : "=f"(r.x), "=f"(r.y) : "l"(v));
    return r.x + r.y;
}

// target = base + barrier_index (only meaningful on threadIdx.x==0)
__device__ __forceinline__ void gsync(unsigned target) {
    __syncthreads();
    if (threadIdx.x == 0) {
        unsigned grp = blockIdx.x >> 3;
        unsigned old;
        asm volatile("atom.release.gpu.global.add.u32 %0, [%1], 1;"
                     : "=r"(old) : "l"(&g_cnt[grp * 32]) : "memory");
        if (old == 7u) {
            unsigned r;
            asm volatile("atom.acq_rel.gpu.global.add.u32 %0, [%1], 1;"
                         : "=r"(r) : "l"(&g_rootc) : "memory");
            if (r == NGRP - 1u) {
                g_rootc = 0u;
#pragma unroll
                for (int g = 0; g < NGRP; g++) g_cnt[g * 32] = 0u;
#pragma unroll
                for (int g = 0; g < NGRP; g++)
                    asm volatile("st.release.gpu.global.u32 [%0], %1;"
                                 :: "l"(&g_flag[g * 32]), "r"(target) : "memory");
            }
        }
        unsigned v;
        do {
            asm volatile("ld.acquire.gpu.global.u32 %0, [%1];"
                         : "=r"(v) : "l"(&g_flag[grp * 32]) : "memory");
        } while (v != target);
    }
    __syncthreads();
}

// ------------------------------------------------------------------
// Round-2 GEMM verbatim (scalar FFMA, 2 blocks/SM, 58% fma pipe).
__global__ __launch_bounds__(256) void sgemm_bias(
    const float* __restrict__ Abase, const int* __restrict__ xidx,
    const float* __restrict__ W, const float* __restrict__ bias,
    float* __restrict__ C, int M, int N, int K)
{
    __shared__ float As[8][128];
    __shared__ float Bs[8][128];

    int tid = threadIdx.x;
    int ty = tid >> 4;
    int tx = tid & 15;
    int rowBase = blockIdx.y * 128;
    int colBase = blockIdx.x * 128;

    int arow  = tid >> 1;
    int acol4 = (tid & 1) * 4;
    int am = rowBase + arow;
    const float* arowptr;
    if (xidx) arowptr = Abase + (size_t)xidx[am] * K;
    else      arowptr = Abase + (size_t)am * K;

    int brow  = tid >> 5;
    int bcol4 = (tid & 31) * 4;

    float acc[8][8];
#pragma unroll
    for (int i = 0; i < 8; i++)
#pragma unroll
        for (int j = 0; j < 8; j++) acc[i][j] = 0.f;

    for (int k0 = 0; k0 < K; k0 += 8) {
        float4 av = *(const float4*)&arowptr[k0 + acol4];
        As[acol4 + 0][arow] = av.x;
        As[acol4 + 1][arow] = av.y;
        As[acol4 + 2][arow] = av.z;
        As[acol4 + 3][arow] = av.w;

        float4 bv = *(const float4*)&W[(size_t)(k0 + brow) * N + colBase + bcol4];
        *(float4*)&Bs[brow][bcol4] = bv;

        __syncthreads();
#pragma unroll
        for (int kk = 0; kk < 8; kk++) {
            float4 a0 = *(const float4*)&As[kk][ty * 8];
            float4 a1 = *(const float4*)&As[kk][ty * 8 + 4];
            float4 b0 = *(const float4*)&Bs[kk][tx * 8];
            float4 b1 = *(const float4*)&Bs[kk][tx * 8 + 4];
            float ar[8] = {a0.x,a0.y,a0.z,a0.w,a1.x,a1.y,a1.z,a1.w};
            float br[8] = {b0.x,b0.y,b0.z,b0.w,b1.x,b1.y,b1.z,b1.w};
#pragma unroll
            for (int i = 0; i < 8; i++)
#pragma unroll
                for (int j = 0; j < 8; j++)
                    acc[i][j] = fmaf(ar[i], br[j], acc[i][j]);
        }
        __syncthreads();
    }

    int col0 = colBase + tx * 8;
    float4 bia0 = *(const float4*)&bias[col0];
    float4 bia1 = *(const float4*)&bias[col0 + 4];
#pragma unroll
    for (int i = 0; i < 8; i++) {
        int row = rowBase + ty * 8 + i;
        float4 v0, v1;
        v0.x = acc[i][0] + bia0.x; v0.y = acc[i][1] + bia0.y;
        v0.z = acc[i][2] + bia0.z; v0.w = acc[i][3] + bia0.w;
        v1.x = acc[i][4] + bia1.x; v1.y = acc[i][5] + bia1.y;
        v1.z = acc[i][6] + bia1.z; v1.w = acc[i][7] + bia1.w;
        *(float4*)&C[(size_t)row * N + col0]     = v0;
        *(float4*)&C[(size_t)row * N + col0 + 4] = v1;
    }
}

// ------------------------------------------------------------------
// Persistent GRU scan (round-4 compute, new barrier).
#define SWG_BYTES 65664
#define SWC_BYTES 32896
#define SH_BYTES  131072
#define SMEM_BYTES (SWG_BYTES + SWC_BYTES + SH_BYTES)

__global__ __launch_bounds__(NTHR) void gru_scan(
    const float* __restrict__ Wgh,   // [1024][2048]
    const float* __restrict__ Wch,   // [1024][1024]
    const float* __restrict__ Xg,    // [16384][2048]
    const float* __restrict__ Xc,    // [16384][1024]
    const float* __restrict__ h0,
    float* __restrict__ y,
    float* __restrict__ s_out)
{
    extern __shared__ char smraw[];
    char*  swg = smraw;
    char*  swc = smraw + SWG_BYTES;
    float* sh  = (float*)(smraw + SWG_BYTES + SWC_BYTES);
    ull*   red = (ull*)sh;

    const int tid = threadIdx.x;
    const int blk = blockIdx.x;
    const int kh  = tid >> 8;
    const int r   = tid & 255;
    const int b   = r >> 3;
    const int jj  = r & 7;
    const int jg0 = blk * 16;
    const int jc0 = blk * 8;

    // barrier generation base (flag value persists across launches/replays;
    // safe: flag can't advance until every block's thread0 has arrived,
    // which is program-ordered after this read)
    unsigned base = 0, nb = 0;
    if (tid == 0) base = g_flag[(blk >> 3) * 32];

    // ---- preload W slices, transposed (once per layer) ----
    for (int i = tid; i < 4096; i += NTHR) {
        int k = i >> 2, c4 = (i & 3) * 4;
        float4 v = *(const float4*)&Wgh[(size_t)k * U2 + jg0 + c4];
        float vv[4] = {v.x, v.y, v.z, v.w};
#pragma unroll
        for (int d = 0; d < 4; d++) {
            int c = c4 + d;
            *(float*)(swg + (c >> 1) * 8208 + (c & 1) * 4096 + k * 4) = vv[d];
        }
    }
    for (int i = tid; i < 2048; i += NTHR) {
        int k = i >> 1, cb = (i & 1) * 4;
        float4 v = *(const float4*)&Wch[(size_t)k * Uz + jc0 + cb];
        float vv[4] = {v.x, v.y, v.z, v.w};
#pragma unroll
        for (int d = 0; d < 4; d++)
            *(float*)(swc + (cb + d) * 4112 + k * 4) = vv[d];
    }
    {
        int i = blk * NTHR + tid;
        if (i < Bz * Uz) __stcg(&g_h[i], h0[i]);
    }
    nb++; gsync(base + nb);

    for (int t = 0; t < Sz; t++) {
        // ======== phase 1: stage h, compute gates ========
        {
            const float4* src = (const float4*)g_h;
            float4* dst = (float4*)sh;
#pragma unroll 4
            for (int rr = 0; rr < 16; rr++) {
                int i = tid + rr * NTHR;
                dst[i] = __ldcg(src + i);
            }
        }
        __syncthreads();

        ull acc0a = 0, acc0b = 0, acc1a = 0, acc1b = 0;
        {
            const ulonglong2* hp  = (const ulonglong2*)(sh + b * 1024 + kh * 512);
            const ulonglong2* w0p = (const ulonglong2*)(swg + jj * 8208 + kh * 2048);
            const ulonglong2* w1p = (const ulonglong2*)(swg + jj * 8208 + 4096 + kh * 2048);
#pragma unroll 2
            for (int i = 0; i < 128; i += 4) {
                ulonglong2 h0v = hp[i], h1v = hp[i+1], h2v = hp[i+2], h3v = hp[i+3];
                ulonglong2 a0 = w0p[i], a1 = w0p[i+1], a2 = w0p[i+2], a3 = w0p[i+3];
                fma2(acc0a, h0v.x, a0.x); fma2(acc0b, h0v.y, a0.y);
                fma2(acc0a, h1v.x, a1.x); fma2(acc0b, h1v.y, a1.y);
                fma2(acc0a, h2v.x, a2.x); fma2(acc0b, h2v.y, a2.y);
                fma2(acc0a, h3v.x, a3.x); fma2(acc0b, h3v.y, a3.y);
                ulonglong2 b0 = w1p[i], b1 = w1p[i+1], b2 = w1p[i+2], b3 = w1p[i+3];
                fma2(acc1a, h0v.x, b0.x); fma2(acc1b, h0v.y, b0.y);
                fma2(acc1a, h1v.x, b1.x); fma2(acc1b, h1v.y, b1.y);
                fma2(acc1a, h2v.x, b2.x); fma2(acc1b, h2v.y, b2.y);
                fma2(acc1a, h3v.x, b3.x); fma2(acc1b, h3v.y, b3.y);
            }
        }
        add2(acc0a, acc0b);
        add2(acc1a, acc1b);

        __syncthreads();
        if (kh) { red[r * 2] = acc0a; red[r * 2 + 1] = acc1a; }
        __syncthreads();
        if (!kh) {
            add2(acc0a, red[r * 2]);
            add2(acc1a, red[r * 2 + 1]);
            float s0 = hadd2(acc0a);
            float s1 = hadd2(acc1a);
            int jg = jg0 + jj * 2;
            int m  = b * Sz + t;
            float2 xg = *(const float2*)&Xg[(size_t)m * U2 + jg];
            float v0 = 1.f / (1.f + expf(-(xg.x + s0)));
            float v1 = 1.f / (1.f + expf(-(xg.y + s1)));
            if (jg < Uz) {
                float2 hv = __ldcg((const float2*)&g_h[b * Uz + jg]);
                __stcg((float2*)&g_a[b * Uz + jg], make_float2(v0 * hv.x, v1 * hv.y));
            } else {
                __stcg((float2*)&g_u[b * Uz + jg - Uz], make_float2(v0, v1));
            }
        }
        nb++; gsync(base + nb);

        // ======== phase 2: stage a, compute candidate + update ========
        {
            const float4* src = (const float4*)g_a;
            float4* dst = (float4*)sh;
#pragma unroll 4
            for (int rr = 0; rr < 16; rr++) {
                int i = tid + rr * NTHR;
                dst[i] = __ldcg(src + i);
            }
        }
        __syncthreads();

        ull ca = 0, cb2 = 0;
        {
            const ulonglong2* ap = (const ulonglong2*)(sh + b * 1024 + kh * 512);
            const ulonglong2* wp = (const ulonglong2*)(swc + jj * 4112 + kh * 2048);
#pragma unroll 2
            for (int i = 0; i < 128; i += 4) {
                ulonglong2 a0 = ap[i], a1 = ap[i+1], a2 = ap[i+2], a3 = ap[i+3];
                ulonglong2 w0 = wp[i], w1 = wp[i+1], w2 = wp[i+2], w3 = wp[i+3];
                fma2(ca, a0.x, w0.x); fma2(cb2, a0.y, w0.y);
                fma2(ca, a1.x, w1.x); fma2(cb2, a1.y, w1.y);
                fma2(ca, a2.x, w2.x); fma2(cb2, a2.y, w2.y);
                fma2(ca, a3.x, w3.x); fma2(cb2, a3.y, w3.y);
            }
        }
        add2(ca, cb2);

        __syncthreads();
        if (kh) red[r] = ca;
        __syncthreads();
        if (!kh) {
            add2(ca, red[r]);
            float cs = hadd2(ca);
            int jc = jc0 + jj;
            int m  = b * Sz + t;
            float c  = tanhf(Xc[(size_t)m * Uz + jc] + cs);
            float uu = __ldcg(&g_u[b * Uz + jc]);
            float ho = __ldcg(&g_h[b * Uz + jc]);
            float hn = uu * ho + (1.f - uu) * c;
            __stcg(&g_h[b * Uz + jc], hn);
            y[(size_t)m * Uz + jc] = hn;
        }
        nb++; gsync(base + nb);
    }

    {
        int i = blk * NTHR + tid;
        if (i < Bz * Uz) s_out[i] = __ldcg(&g_h[i]);
    }
}

// ------------------------------------------------------------------
extern "C" void kernel_launch(void* const* d_in, const int* in_sizes, int n_in,
                              void* d_out, int out_size)
{
    const int*   x    = (const int*)  d_in[0];
    const float* h0_0 = (const float*)d_in[1];
    const float* h0_1 = (const float*)d_in[2];
    const float* emb  = (const float*)d_in[3];
    const float* Wg0  = (const float*)d_in[4];
    const float* bg0  = (const float*)d_in[5];
    const float* Wc0  = (const float*)d_in[6];
    const float* bc0  = (const float*)d_in[7];
    const float* Wg1  = (const float*)d_in[8];
    const float* bg1  = (const float*)d_in[9];
    const float* Wc1  = (const float*)d_in[10];
    const float* bc1  = (const float*)d_in[11];
    float* out = (float*)d_out;

    float *Xg, *Xc, *y0;
    cudaGetSymbolAddress((void**)&Xg, g_Xg);
    cudaGetSymbolAddress((void**)&Xc, g_Xc);
    cudaGetSymbolAddress((void**)&y0, g_y0);

    static int smem_set = 0;
    if (!smem_set) {
        cudaFuncSetAttribute(gru_scan, cudaFuncAttributeMaxDynamicSharedMemorySize, SMEM_BYTES);
        smem_set = 1;
    }

    float* s0_out = out + (size_t)BSz * Uz;
    float* s1_out = s0_out + Bz * Uz;

    // ---------- layer 0 ----------
    sgemm_bias<<<dim3(U2 / 128, BSz / 128), 256>>>(emb, x, Wg0, bg0, Xg, BSz, U2, Ez);
    sgemm_bias<<<dim3(Uz / 128, BSz / 128), 256>>>(emb, x, Wc0, bc0, Xc, BSz, Uz, Ez);
    gru_scan<<<NBLK, NTHR, SMEM_BYTES>>>(
        Wg0 + (size_t)Ez * U2, Wc0 + (size_t)Ez * Uz, Xg, Xc, h0_0, y0, s0_out);

    // ---------- layer 1 ----------
    sgemm_bias<<<dim3(U2 / 128, BSz / 128), 256>>>(y0, nullptr, Wg1, bg1, Xg, BSz, U2, Uz);
    sgemm_bias<<<dim3(Uz / 128, BSz / 128), 256>>>(y0, nullptr, Wc1, bc1, Xc, BSz, Uz, Uz);
    gru_scan<<<NBLK, NTHR, SMEM_BYTES>>>(
        Wg1 + (size_t)Uz * U2, Wc1 + (size_t)Uz * Uz, Xg, Xc, h0_1, out, s1_out);
}

// round 6
// speedup vs baseline: 1.5322x; 1.5322x over previous
#include <cuda_runtime.h>
#include <math.h>
#include <stdint.h>

typedef unsigned long long ull;

#define Bz 32
#define Sz 512
#define Ez 256
#define Uz 1024
#define U2 2048
#define BSz (Bz*Sz)   // 16384

#define NBLK 128
#define NTHR 512

// -------- scratch (device globals; no allocation allowed) --------
__device__ float g_Xg[(size_t)BSz * U2];
__device__ float g_Xc[(size_t)BSz * Uz];
__device__ float g_y0[(size_t)BSz * Uz];
__device__ float g_h [Bz * Uz];
__device__ float g_u [Bz * Uz];
__device__ float g_a [Bz * Uz];

// -------- monotonic grid barrier --------
__device__ unsigned g_ctr  = 0;   // never reset; wraps safely
__device__ unsigned g_base = 0;   // snapshot before each scan launch

__global__ void set_base() { g_base = g_ctr; }

__device__ __forceinline__ void gsync(unsigned tgt) {
    __syncthreads();
    if (threadIdx.x == 0) {
        unsigned old;
        asm volatile("atom.add.release.gpu.global.u32 %0, [%1], 1;"
                     : "=r"(old) : "l"(&g_ctr) : "memory");
        unsigned v;
        for (;;) {
            asm volatile("ld.acquire.gpu.global.u32 %0, [%1];"
                         : "=r"(v) : "l"(&g_ctr) : "memory");
            if ((int)(v - tgt) >= 0) break;
            __nanosleep(40);
        }
    }
    __syncthreads();
}

// -------- f32x2 packed-math helpers (pack axis = k) --------
__device__ __forceinline__ void fma2(ull& d, ull a, ull b) {
    asm("fma.rn.f32x2 %0, %1, %2, %0;" : "+l"(d) : "l"(a), "l"(b));
}
__device__ __forceinline__ void add2(ull& d, ull a) {
    asm("add.rn.f32x2 %0, %1, %0;" : "+l"(d) : "l"(a));
}
__device__ __forceinline__ float hadd2(ull v) {
    float2 r; asm("mov.b64 {%0,%1}, %2;" : "=f"(r.x), "=f"(r.y) : "l"(v));
    return r.x + r.y;
}

__device__ __forceinline__ void cpasync16(uint32_t s, const void* g) {
    asm volatile("cp.async.cg.shared.global [%0], [%1], 16;"
                 :: "r"(s), "l"(g) : "memory");
}
__device__ __forceinline__ void cpasync_wait() {
    asm volatile("cp.async.commit_group;\ncp.async.wait_group 0;" ::: "memory");
}

// ------------------------------------------------------------------
// Round-2 GEMM verbatim (scalar FFMA, 2 blocks/SM, 58% fma pipe).
__global__ __launch_bounds__(256) void sgemm_bias(
    const float* __restrict__ Abase, const int* __restrict__ xidx,
    const float* __restrict__ W, const float* __restrict__ bias,
    float* __restrict__ C, int M, int N, int K)
{
    __shared__ float As[8][128];
    __shared__ float Bs[8][128];

    int tid = threadIdx.x;
    int ty = tid >> 4;
    int tx = tid & 15;
    int rowBase = blockIdx.y * 128;
    int colBase = blockIdx.x * 128;

    int arow  = tid >> 1;
    int acol4 = (tid & 1) * 4;
    int am = rowBase + arow;
    const float* arowptr;
    if (xidx) arowptr = Abase + (size_t)xidx[am] * K;
    else      arowptr = Abase + (size_t)am * K;

    int brow  = tid >> 5;
    int bcol4 = (tid & 31) * 4;

    float acc[8][8];
#pragma unroll
    for (int i = 0; i < 8; i++)
#pragma unroll
        for (int j = 0; j < 8; j++) acc[i][j] = 0.f;

    for (int k0 = 0; k0 < K; k0 += 8) {
        float4 av = *(const float4*)&arowptr[k0 + acol4];
        As[acol4 + 0][arow] = av.x;
        As[acol4 + 1][arow] = av.y;
        As[acol4 + 2][arow] = av.z;
        As[acol4 + 3][arow] = av.w;

        float4 bv = *(const float4*)&W[(size_t)(k0 + brow) * N + colBase + bcol4];
        *(float4*)&Bs[brow][bcol4] = bv;

        __syncthreads();
#pragma unroll
        for (int kk = 0; kk < 8; kk++) {
            float4 a0 = *(const float4*)&As[kk][ty * 8];
            float4 a1 = *(const float4*)&As[kk][ty * 8 + 4];
            float4 b0 = *(const float4*)&Bs[kk][tx * 8];
            float4 b1 = *(const float4*)&Bs[kk][tx * 8 + 4];
            float ar[8] = {a0.x,a0.y,a0.z,a0.w,a1.x,a1.y,a1.z,a1.w};
            float br[8] = {b0.x,b0.y,b0.z,b0.w,b1.x,b1.y,b1.z,b1.w};
#pragma unroll
            for (int i = 0; i < 8; i++)
#pragma unroll
                for (int j = 0; j < 8; j++)
                    acc[i][j] = fmaf(ar[i], br[j], acc[i][j]);
        }
        __syncthreads();
    }

    int col0 = colBase + tx * 8;
    float4 bia0 = *(const float4*)&bias[col0];
    float4 bia1 = *(const float4*)&bias[col0 + 4];
#pragma unroll
    for (int i = 0; i < 8; i++) {
        int row = rowBase + ty * 8 + i;
        float4 v0, v1;
        v0.x = acc[i][0] + bia0.x; v0.y = acc[i][1] + bia0.y;
        v0.z = acc[i][2] + bia0.z; v0.w = acc[i][3] + bia0.w;
        v1.x = acc[i][4] + bia1.x; v1.y = acc[i][5] + bia1.y;
        v1.z = acc[i][6] + bia1.z; v1.w = acc[i][7] + bia1.w;
        *(float4*)&C[(size_t)row * N + col0]     = v0;
        *(float4*)&C[(size_t)row * N + col0 + 4] = v1;
    }
}

// ------------------------------------------------------------------
// Persistent GRU scan. 128 blocks x 512 threads.
// tid -> b = tid>>4 (batch), kh = (tid>>3)&1 (k-half, a LANE bit -> shfl
// reduction), jj = tid&7.
// Phase1: thread computes gate cols jg0+2jj, jg0+2jj+1 over its 512-k half.
// Phase2: thread computes cand col jc0+jj over its 512-k half.
// W transposed [col][k] in SMEM (k-contiguous f32x2); h/a staged whole via
// cp.async once per phase.
#define SWG_BYTES 65664
#define SWC_BYTES 32896
#define SH_BYTES  131072
#define SMEM_BYTES (SWG_BYTES + SWC_BYTES + SH_BYTES)

__global__ __launch_bounds__(NTHR) void gru_scan(
    const float* __restrict__ Wgh,   // [1024][2048]
    const float* __restrict__ Wch,   // [1024][1024]
    const float* __restrict__ Xg,    // [16384][2048]
    const float* __restrict__ Xc,    // [16384][1024]
    const float* __restrict__ h0,
    float* __restrict__ y,
    float* __restrict__ s_out)
{
    extern __shared__ char smraw[];
    char*  swg = smraw;
    char*  swc = smraw + SWG_BYTES;
    float* sh  = (float*)(smraw + SWG_BYTES + SWC_BYTES);

    const int tid = threadIdx.x;
    const int blk = blockIdx.x;
    const int b   = tid >> 4;        // 0..31
    const int kh  = (tid >> 3) & 1;  // lane bit 3
    const int jj  = tid & 7;
    const int jg0 = blk * 16;
    const int jc0 = blk * 8;

    unsigned base = 0, nb = 0;
    if (tid == 0) base = g_base;

    const uint32_t sh_s = (uint32_t)__cvta_generic_to_shared(sh);

    // ---- preload W slices, transposed (once per layer) ----
    for (int i = tid; i < 4096; i += NTHR) {
        int k = i >> 2, c4 = (i & 3) * 4;
        float4 v = *(const float4*)&Wgh[(size_t)k * U2 + jg0 + c4];
        float vv[4] = {v.x, v.y, v.z, v.w};
#pragma unroll
        for (int d = 0; d < 4; d++) {
            int c = c4 + d;
            *(float*)(swg + (c >> 1) * 8208 + (c & 1) * 4096 + k * 4) = vv[d];
        }
    }
    for (int i = tid; i < 2048; i += NTHR) {
        int k = i >> 1, cb = (i & 1) * 4;
        float4 v = *(const float4*)&Wch[(size_t)k * Uz + jc0 + cb];
        float vv[4] = {v.x, v.y, v.z, v.w};
#pragma unroll
        for (int d = 0; d < 4; d++)
            *(float*)(swc + (cb + d) * 4112 + k * 4) = vv[d];
    }
    {
        int i = blk * NTHR + tid;
        if (i < Bz * Uz) __stcg(&g_h[i], h0[i]);
    }
    nb++; gsync(base + nb * NBLK);

    for (int t = 0; t < Sz; t++) {
        // ======== phase 1: stage h (cp.async), compute gates ========
#pragma unroll 4
        for (int rr = 0; rr < 16; rr++) {
            int i = tid + rr * NTHR;
            cpasync16(sh_s + i * 16, (const char*)g_h + i * 16);
        }
        cpasync_wait();
        __syncthreads();

        ull acc0a = 0, acc0b = 0, acc1a = 0, acc1b = 0;
        {
            const ulonglong2* hp  = (const ulonglong2*)(sh + b * 1024 + kh * 512);
            const ulonglong2* w0p = (const ulonglong2*)(swg + jj * 8208 + kh * 2048);
            const ulonglong2* w1p = (const ulonglong2*)(swg + jj * 8208 + 4096 + kh * 2048);
#pragma unroll 2
            for (int i = 0; i < 128; i += 4) {
                ulonglong2 h0v = hp[i], h1v = hp[i+1], h2v = hp[i+2], h3v = hp[i+3];
                ulonglong2 a0 = w0p[i], a1 = w0p[i+1], a2 = w0p[i+2], a3 = w0p[i+3];
                fma2(acc0a, h0v.x, a0.x); fma2(acc0b, h0v.y, a0.y);
                fma2(acc0a, h1v.x, a1.x); fma2(acc0b, h1v.y, a1.y);
                fma2(acc0a, h2v.x, a2.x); fma2(acc0b, h2v.y, a2.y);
                fma2(acc0a, h3v.x, a3.x); fma2(acc0b, h3v.y, a3.y);
                ulonglong2 b0 = w1p[i], b1 = w1p[i+1], b2 = w1p[i+2], b3 = w1p[i+3];
                fma2(acc1a, h0v.x, b0.x); fma2(acc1b, h0v.y, b0.y);
                fma2(acc1a, h1v.x, b1.x); fma2(acc1b, h1v.y, b1.y);
                fma2(acc1a, h2v.x, b2.x); fma2(acc1b, h2v.y, b2.y);
                fma2(acc1a, h3v.x, b3.x); fma2(acc1b, h3v.y, b3.y);
            }
        }
        add2(acc0a, acc0b);
        add2(acc1a, acc1b);
        // reduce across kh (lane bit 3)
        acc0a += 0; // keep ptxas from reordering weirdly
        {
            ull o0 = __shfl_xor_sync(0xFFFFFFFFu, acc0a, 8);
            ull o1 = __shfl_xor_sync(0xFFFFFFFFu, acc1a, 8);
            add2(acc0a, o0);
            add2(acc1a, o1);
        }
        if (kh == 0) {
            float s0 = hadd2(acc0a);
            float s1 = hadd2(acc1a);
            int jg = jg0 + jj * 2;
            int m  = b * Sz + t;
            float2 xg = *(const float2*)&Xg[(size_t)m * U2 + jg];
            float v0 = 1.f / (1.f + expf(-(xg.x + s0)));
            float v1 = 1.f / (1.f + expf(-(xg.y + s1)));
            if (jg < Uz) {
                float2 hv = __ldcg((const float2*)&g_h[b * Uz + jg]);
                __stcg((float2*)&g_a[b * Uz + jg], make_float2(v0 * hv.x, v1 * hv.y));
            } else {
                __stcg((float2*)&g_u[b * Uz + jg - Uz], make_float2(v0, v1));
            }
        }
        nb++; gsync(base + nb * NBLK);

        // ======== phase 2: stage a (cp.async), candidate + update ========
#pragma unroll 4
        for (int rr = 0; rr < 16; rr++) {
            int i = tid + rr * NTHR;
            cpasync16(sh_s + i * 16, (const char*)g_a + i * 16);
        }
        cpasync_wait();
        __syncthreads();

        ull ca = 0, cb2 = 0;
        {
            const ulonglong2* ap = (const ulonglong2*)(sh + b * 1024 + kh * 512);
            const ulonglong2* wp = (const ulonglong2*)(swc + jj * 4112 + kh * 2048);
#pragma unroll 2
            for (int i = 0; i < 128; i += 4) {
                ulonglong2 a0 = ap[i], a1 = ap[i+1], a2 = ap[i+2], a3 = ap[i+3];
                ulonglong2 w0 = wp[i], w1 = wp[i+1], w2 = wp[i+2], w3 = wp[i+3];
                fma2(ca, a0.x, w0.x); fma2(cb2, a0.y, w0.y);
                fma2(ca, a1.x, w1.x); fma2(cb2, a1.y, w1.y);
                fma2(ca, a2.x, w2.x); fma2(cb2, a2.y, w2.y);
                fma2(ca, a3.x, w3.x); fma2(cb2, a3.y, w3.y);
            }
        }
        add2(ca, cb2);
        {
            ull oc = __shfl_xor_sync(0xFFFFFFFFu, ca, 8);
            add2(ca, oc);
        }
        if (kh == 0) {
            float cs = hadd2(ca);
            int jc = jc0 + jj;
            int m  = b * Sz + t;
            float c  = tanhf(Xc[(size_t)m * Uz + jc] + cs);
            float uu = __ldcg(&g_u[b * Uz + jc]);
            float ho = __ldcg(&g_h[b * Uz + jc]);
            float hn = uu * ho + (1.f - uu) * c;
            __stcg(&g_h[b * Uz + jc], hn);
            y[(size_t)m * Uz + jc] = hn;
        }
        nb++; gsync(base + nb * NBLK);
    }

    {
        int i = blk * NTHR + tid;
        if (i < Bz * Uz) s_out[i] = __ldcg(&g_h[i]);
    }
}

// ------------------------------------------------------------------
extern "C" void kernel_launch(void* const* d_in, const int* in_sizes, int n_in,
                              void* d_out, int out_size)
{
    const int*   x    = (const int*)  d_in[0];
    const float* h0_0 = (const float*)d_in[1];
    const float* h0_1 = (const float*)d_in[2];
    const float* emb  = (const float*)d_in[3];
    const float* Wg0  = (const float*)d_in[4];
    const float* bg0  = (const float*)d_in[5];
    const float* Wc0  = (const float*)d_in[6];
    const float* bc0  = (const float*)d_in[7];
    const float* Wg1  = (const float*)d_in[8];
    const float* bg1  = (const float*)d_in[9];
    const float* Wc1  = (const float*)d_in[10];
    const float* bc1  = (const float*)d_in[11];
    float* out = (float*)d_out;

    float *Xg, *Xc, *y0;
    cudaGetSymbolAddress((void**)&Xg, g_Xg);
    cudaGetSymbolAddress((void**)&Xc, g_Xc);
    cudaGetSymbolAddress((void**)&y0, g_y0);

    static int smem_set = 0;
    if (!smem_set) {
        cudaFuncSetAttribute(gru_scan, cudaFuncAttributeMaxDynamicSharedMemorySize, SMEM_BYTES);
        smem_set = 1;
    }

    float* s0_out = out + (size_t)BSz * Uz;
    float* s1_out = s0_out + Bz * Uz;

    // ---------- layer 0 ----------
    sgemm_bias<<<dim3(U2 / 128, BSz / 128), 256>>>(emb, x, Wg0, bg0, Xg, BSz, U2, Ez);
    sgemm_bias<<<dim3(Uz / 128, BSz / 128), 256>>>(emb, x, Wc0, bc0, Xc, BSz, Uz, Ez);
    set_base<<<1, 1>>>();
    gru_scan<<<NBLK, NTHR, SMEM_BYTES>>>(
        Wg0 + (size_t)Ez * U2, Wc0 + (size_t)Ez * Uz, Xg, Xc, h0_0, y0, s0_out);

    // ---------- layer 1 ----------
    sgemm_bias<<<dim3(U2 / 128, BSz / 128), 256>>>(y0, nullptr, Wg1, bg1, Xg, BSz, U2, Uz);
    sgemm_bias<<<dim3(Uz / 128, BSz / 128), 256>>>(y0, nullptr, Wc1, bc1, Xc, BSz, Uz, Uz);
    set_base<<<1, 1>>>();
    gru_scan<<<NBLK, NTHR, SMEM_BYTES>>>(
        Wg1 + (size_t)Uz * U2, Wc1 + (size_t)Uz * Uz, Xg, Xc, h0_1, out, s1_out);
}

// round 7
// speedup vs baseline: 1.5334x; 1.0008x over previous
#include <cuda_runtime.h>
#include <math.h>
#include <stdint.h>

typedef unsigned long long ull;

#define Bz 32
#define Sz 512
#define Ez 256
#define Uz 1024
#define U2 2048
#define BSz (Bz*Sz)   // 16384

#define NBLK 128
#define NTHR 512

// -------- scratch (device globals; no allocation allowed) --------
__device__ float g_Xg[(size_t)BSz * U2];
__device__ float g_Xc[(size_t)BSz * Uz];
__device__ float g_y0[(size_t)BSz * Uz];
__device__ float g_h [Bz * Uz];
__device__ float g_u [Bz * Uz];
__device__ float g_a [Bz * Uz];

// -------- monotonic grid barrier --------
__device__ unsigned g_ctr  = 0;   // never reset; wraps safely
__device__ unsigned g_base = 0;   // snapshot before each scan launch

__global__ void set_base() { g_base = g_ctr; }

__device__ __forceinline__ void gsync(unsigned tgt) {
    __syncthreads();
    if (threadIdx.x == 0) {
        unsigned old;
        asm volatile("atom.add.release.gpu.global.u32 %0, [%1], 1;"
                     : "=r"(old) : "l"(&g_ctr) : "memory");
        unsigned v;
        for (;;) {
            asm volatile("ld.acquire.gpu.global.u32 %0, [%1];"
                         : "=r"(v) : "l"(&g_ctr) : "memory");
            if ((int)(v - tgt) >= 0) break;
            __nanosleep(40);
        }
    }
    __syncthreads();
}

// -------- f32x2 packed-math helpers (pack axis = k) --------
__device__ __forceinline__ void fma2(ull& d, ull a, ull b) {
    asm("fma.rn.f32x2 %0, %1, %2, %0;" : "+l"(d) : "l"(a), "l"(b));
}
__device__ __forceinline__ void add2(ull& d, ull a) {
    asm("add.rn.f32x2 %0, %1, %0;" : "+l"(d) : "l"(a));
}
__device__ __forceinline__ float hadd2(ull v) {
    float2 r; asm("mov.b64 {%0,%1}, %2;" : "=f"(r.x), "=f"(r.y) : "l"(v));
    return r.x + r.y;
}

__device__ __forceinline__ void cpasync16(uint32_t s, const void* g) {
    asm volatile("cp.async.cg.shared.global [%0], [%1], 16;"
                 :: "r"(s), "l"(g) : "memory");
}
__device__ __forceinline__ void cpasync_wait() {
    asm volatile("cp.async.commit_group;\ncp.async.wait_group 0;" ::: "memory");
}

// ------------------------------------------------------------------
// Round-2 GEMM verbatim (scalar FFMA, 2 blocks/SM, 58% fma pipe).
__global__ __launch_bounds__(256) void sgemm_bias(
    const float* __restrict__ Abase, const int* __restrict__ xidx,
    const float* __restrict__ W, const float* __restrict__ bias,
    float* __restrict__ C, int M, int N, int K)
{
    __shared__ float As[8][128];
    __shared__ float Bs[8][128];

    int tid = threadIdx.x;
    int ty = tid >> 4;
    int tx = tid & 15;
    int rowBase = blockIdx.y * 128;
    int colBase = blockIdx.x * 128;

    int arow  = tid >> 1;
    int acol4 = (tid & 1) * 4;
    int am = rowBase + arow;
    const float* arowptr;
    if (xidx) arowptr = Abase + (size_t)xidx[am] * K;
    else      arowptr = Abase + (size_t)am * K;

    int brow  = tid >> 5;
    int bcol4 = (tid & 31) * 4;

    float acc[8][8];
#pragma unroll
    for (int i = 0; i < 8; i++)
#pragma unroll
        for (int j = 0; j < 8; j++) acc[i][j] = 0.f;

    for (int k0 = 0; k0 < K; k0 += 8) {
        float4 av = *(const float4*)&arowptr[k0 + acol4];
        As[acol4 + 0][arow] = av.x;
        As[acol4 + 1][arow] = av.y;
        As[acol4 + 2][arow] = av.z;
        As[acol4 + 3][arow] = av.w;

        float4 bv = *(const float4*)&W[(size_t)(k0 + brow) * N + colBase + bcol4];
        *(float4*)&Bs[brow][bcol4] = bv;

        __syncthreads();
#pragma unroll
        for (int kk = 0; kk < 8; kk++) {
            float4 a0 = *(const float4*)&As[kk][ty * 8];
            float4 a1 = *(const float4*)&As[kk][ty * 8 + 4];
            float4 b0 = *(const float4*)&Bs[kk][tx * 8];
            float4 b1 = *(const float4*)&Bs[kk][tx * 8 + 4];
            float ar[8] = {a0.x,a0.y,a0.z,a0.w,a1.x,a1.y,a1.z,a1.w};
            float br[8] = {b0.x,b0.y,b0.z,b0.w,b1.x,b1.y,b1.z,b1.w};
#pragma unroll
            for (int i = 0; i < 8; i++)
#pragma unroll
                for (int j = 0; j < 8; j++)
                    acc[i][j] = fmaf(ar[i], br[j], acc[i][j]);
        }
        __syncthreads();
    }

    int col0 = colBase + tx * 8;
    float4 bia0 = *(const float4*)&bias[col0];
    float4 bia1 = *(const float4*)&bias[col0 + 4];
#pragma unroll
    for (int i = 0; i < 8; i++) {
        int row = rowBase + ty * 8 + i;
        float4 v0, v1;
        v0.x = acc[i][0] + bia0.x; v0.y = acc[i][1] + bia0.y;
        v0.z = acc[i][2] + bia0.z; v0.w = acc[i][3] + bia0.w;
        v1.x = acc[i][4] + bia1.x; v1.y = acc[i][5] + bia1.y;
        v1.z = acc[i][6] + bia1.z; v1.w = acc[i][7] + bia1.w;
        *(float4*)&C[(size_t)row * N + col0]     = v0;
        *(float4*)&C[(size_t)row * N + col0 + 4] = v1;
    }
}

// ------------------------------------------------------------------
// Persistent GRU scan. 128 blocks x 512 threads.
// tid -> b = tid>>4 (batch), kh = (tid>>3)&1 (k-half, a LANE bit -> shfl
// reduction), jj = tid&7.
// Phase1: thread computes gate cols jg0+2jj, jg0+2jj+1 over its 512-k half.
// Phase2: thread computes cand col jc0+jj over its 512-k half.
// W transposed [col][k] in SMEM (k-contiguous f32x2); h/a staged whole via
// cp.async once per phase.
#define SWG_BYTES 65664
#define SWC_BYTES 32896
#define SH_BYTES  131072
#define SMEM_BYTES (SWG_BYTES + SWC_BYTES + SH_BYTES)

__global__ __launch_bounds__(NTHR) void gru_scan(
    const float* __restrict__ Wgh,   // [1024][2048]
    const float* __restrict__ Wch,   // [1024][1024]
    const float* __restrict__ Xg,    // [16384][2048]
    const float* __restrict__ Xc,    // [16384][1024]
    const float* __restrict__ h0,
    float* __restrict__ y,
    float* __restrict__ s_out)
{
    extern __shared__ char smraw[];
    char*  swg = smraw;
    char*  swc = smraw + SWG_BYTES;
    float* sh  = (float*)(smraw + SWG_BYTES + SWC_BYTES);

    const int tid = threadIdx.x;
    const int blk = blockIdx.x;
    const int b   = tid >> 4;        // 0..31
    const int kh  = (tid >> 3) & 1;  // lane bit 3
    const int jj  = tid & 7;
    const int jg0 = blk * 16;
    const int jc0 = blk * 8;

    unsigned base = 0, nb = 0;
    if (tid == 0) base = g_base;

    const uint32_t sh_s = (uint32_t)__cvta_generic_to_shared(sh);

    // ---- preload W slices, transposed (once per layer) ----
    for (int i = tid; i < 4096; i += NTHR) {
        int k = i >> 2, c4 = (i & 3) * 4;
        float4 v = *(const float4*)&Wgh[(size_t)k * U2 + jg0 + c4];
        float vv[4] = {v.x, v.y, v.z, v.w};
#pragma unroll
        for (int d = 0; d < 4; d++) {
            int c = c4 + d;
            *(float*)(swg + (c >> 1) * 8208 + (c & 1) * 4096 + k * 4) = vv[d];
        }
    }
    for (int i = tid; i < 2048; i += NTHR) {
        int k = i >> 1, cb = (i & 1) * 4;
        float4 v = *(const float4*)&Wch[(size_t)k * Uz + jc0 + cb];
        float vv[4] = {v.x, v.y, v.z, v.w};
#pragma unroll
        for (int d = 0; d < 4; d++)
            *(float*)(swc + (cb + d) * 4112 + k * 4) = vv[d];
    }
    {
        int i = blk * NTHR + tid;
        if (i < Bz * Uz) __stcg(&g_h[i], h0[i]);
    }
    nb++; gsync(base + nb * NBLK);

    for (int t = 0; t < Sz; t++) {
        // ======== phase 1: stage h (cp.async), compute gates ========
#pragma unroll 4
        for (int rr = 0; rr < 16; rr++) {
            int i = tid + rr * NTHR;
            cpasync16(sh_s + i * 16, (const char*)g_h + i * 16);
        }
        cpasync_wait();
        __syncthreads();

        ull acc0a = 0, acc0b = 0, acc1a = 0, acc1b = 0;
        {
            const ulonglong2* hp  = (const ulonglong2*)(sh + b * 1024 + kh * 512);
            const ulonglong2* w0p = (const ulonglong2*)(swg + jj * 8208 + kh * 2048);
            const ulonglong2* w1p = (const ulonglong2*)(swg + jj * 8208 + 4096 + kh * 2048);
#pragma unroll 2
            for (int i = 0; i < 128; i += 4) {
                ulonglong2 h0v = hp[i], h1v = hp[i+1], h2v = hp[i+2], h3v = hp[i+3];
                ulonglong2 a0 = w0p[i], a1 = w0p[i+1], a2 = w0p[i+2], a3 = w0p[i+3];
                fma2(acc0a, h0v.x, a0.x); fma2(acc0b, h0v.y, a0.y);
                fma2(acc0a, h1v.x, a1.x); fma2(acc0b, h1v.y, a1.y);
                fma2(acc0a, h2v.x, a2.x); fma2(acc0b, h2v.y, a2.y);
                fma2(acc0a, h3v.x, a3.x); fma2(acc0b, h3v.y, a3.y);
                ulonglong2 b0 = w1p[i], b1 = w1p[i+1], b2 = w1p[i+2], b3 = w1p[i+3];
                fma2(acc1a, h0v.x, b0.x); fma2(acc1b, h0v.y, b0.y);
                fma2(acc1a, h1v.x, b1.x); fma2(acc1b, h1v.y, b1.y);
                fma2(acc1a, h2v.x, b2.x); fma2(acc1b, h2v.y, b2.y);
                fma2(acc1a, h3v.x, b3.x); fma2(acc1b, h3v.y, b3.y);
            }
        }
        add2(acc0a, acc0b);
        add2(acc1a, acc1b);
        // reduce across kh (lane bit 3)
        acc0a += 0; // keep ptxas from reordering weirdly
        {
            ull o0 = __shfl_xor_sync(0xFFFFFFFFu, acc0a, 8);
            ull o1 = __shfl_xor_sync(0xFFFFFFFFu, acc1a, 8);
            add2(acc0a, o0);
            add2(acc1a, o1);
        }
        if (kh == 0) {
            float s0 = hadd2(acc0a);
            float s1 = hadd2(acc1a);
            int jg = jg0 + jj * 2;
            int m  = b * Sz + t;
            float2 xg = *(const float2*)&Xg[(size_t)m * U2 + jg];
            float v0 = 1.f / (1.f + expf(-(xg.x + s0)));
            float v1 = 1.f / (1.f + expf(-(xg.y + s1)));
            if (jg < Uz) {
                float2 hv = __ldcg((const float2*)&g_h[b * Uz + jg]);
                __stcg((float2*)&g_a[b * Uz + jg], make_float2(v0 * hv.x, v1 * hv.y));
            } else {
                __stcg((float2*)&g_u[b * Uz + jg - Uz], make_float2(v0, v1));
            }
        }
        nb++; gsync(base + nb * NBLK);

        // ======== phase 2: stage a (cp.async), candidate + update ========
#pragma unroll 4
        for (int rr = 0; rr < 16; rr++) {
            int i = tid + rr * NTHR;
            cpasync16(sh_s + i * 16, (const char*)g_a + i * 16);
        }
        cpasync_wait();
        __syncthreads();

        ull ca = 0, cb2 = 0;
        {
            const ulonglong2* ap = (const ulonglong2*)(sh + b * 1024 + kh * 512);
            const ulonglong2* wp = (const ulonglong2*)(swc + jj * 4112 + kh * 2048);
#pragma unroll 2
            for (int i = 0; i < 128; i += 4) {
                ulonglong2 a0 = ap[i], a1 = ap[i+1], a2 = ap[i+2], a3 = ap[i+3];
                ulonglong2 w0 = wp[i], w1 = wp[i+1], w2 = wp[i+2], w3 = wp[i+3];
                fma2(ca, a0.x, w0.x); fma2(cb2, a0.y, w0.y);
                fma2(ca, a1.x, w1.x); fma2(cb2, a1.y, w1.y);
                fma2(ca, a2.x, w2.x); fma2(cb2, a2.y, w2.y);
                fma2(ca, a3.x, w3.x); fma2(cb2, a3.y, w3.y);
            }
        }
        add2(ca, cb2);
        {
            ull oc = __shfl_xor_sync(0xFFFFFFFFu, ca, 8);
            add2(ca, oc);
        }
        if (kh == 0) {
            float cs = hadd2(ca);
            int jc = jc0 + jj;
            int m  = b * Sz + t;
            float c  = tanhf(Xc[(size_t)m * Uz + jc] + cs);
            float uu = __ldcg(&g_u[b * Uz + jc]);
            float ho = __ldcg(&g_h[b * Uz + jc]);
            float hn = uu * ho + (1.f - uu) * c;
            __stcg(&g_h[b * Uz + jc], hn);
            y[(size_t)m * Uz + jc] = hn;
        }
        nb++; gsync(base + nb * NBLK);
    }

    {
        int i = blk * NTHR + tid;
        if (i < Bz * Uz) s_out[i] = __ldcg(&g_h[i]);
    }
}

// ------------------------------------------------------------------
extern "C" void kernel_launch(void* const* d_in, const int* in_sizes, int n_in,
                              void* d_out, int out_size)
{
    const int*   x    = (const int*)  d_in[0];
    const float* h0_0 = (const float*)d_in[1];
    const float* h0_1 = (const float*)d_in[2];
    const float* emb  = (const float*)d_in[3];
    const float* Wg0  = (const float*)d_in[4];
    const float* bg0  = (const float*)d_in[5];
    const float* Wc0  = (const float*)d_in[6];
    const float* bc0  = (const float*)d_in[7];
    const float* Wg1  = (const float*)d_in[8];
    const float* bg1  = (const float*)d_in[9];
    const float* Wc1  = (const float*)d_in[10];
    const float* bc1  = (const float*)d_in[11];
    float* out = (float*)d_out;

    float *Xg, *Xc, *y0;
    cudaGetSymbolAddress((void**)&Xg, g_Xg);
    cudaGetSymbolAddress((void**)&Xc, g_Xc);
    cudaGetSymbolAddress((void**)&y0, g_y0);

    static int smem_set = 0;
    if (!smem_set) {
        cudaFuncSetAttribute(gru_scan, cudaFuncAttributeMaxDynamicSharedMemorySize, SMEM_BYTES);
        smem_set = 1;
    }

    float* s0_out = out + (size_t)BSz * Uz;
    float* s1_out = s0_out + Bz * Uz;

    // ---------- layer 0 ----------
    sgemm_bias<<<dim3(U2 / 128, BSz / 128), 256>>>(emb, x, Wg0, bg0, Xg, BSz, U2, Ez);
    sgemm_bias<<<dim3(Uz / 128, BSz / 128), 256>>>(emb, x, Wc0, bc0, Xc, BSz, Uz, Ez);
    set_base<<<1, 1>>>();
    gru_scan<<<NBLK, NTHR, SMEM_BYTES>>>(
        Wg0 + (size_t)Ez * U2, Wc0 + (size_t)Ez * Uz, Xg, Xc, h0_0, y0, s0_out);

    // ---------- layer 1 ----------
    sgemm_bias<<<dim3(U2 / 128, BSz / 128), 256>>>(y0, nullptr, Wg1, bg1, Xg, BSz, U2, Uz);
    sgemm_bias<<<dim3(Uz / 128, BSz / 128), 256>>>(y0, nullptr, Wc1, bc1, Xc, BSz, Uz, Uz);
    set_base<<<1, 1>>>();
    gru_scan<<<NBLK, NTHR, SMEM_BYTES>>>(
        Wg1 + (size_t)Uz * U2, Wc1 + (size_t)Uz * Uz, Xg, Xc, h0_1, out, s1_out);
}

// round 8
// speedup vs baseline: 2.8932x; 1.8868x over previous
#include <cuda_runtime.h>
#include <math.h>
#include <stdint.h>

typedef unsigned long long ull;

#define Bz 32
#define Sz 512
#define Ez 256
#define Uz 1024
#define U2 2048
#define BSz (Bz*Sz)   // 16384

#define NBLK 128
#define NTHR 512

#define PITCH  1028            // floats per h/a row (pitch%32==4 -> bank-staggered)
#define PITCHB (PITCH*4)       // 4112 bytes
#define BULKB  (Bz*PITCHB)     // 131584 bytes staged per phase

// -------- scratch (device globals; no allocation allowed) --------
__device__ float g_Xg[(size_t)BSz * U2];
__device__ float g_Xc[(size_t)BSz * Uz];
__device__ float g_y0[(size_t)BSz * Uz];
__device__ float g_h [Bz * PITCH];
__device__ float g_a [Bz * PITCH];
__device__ float g_u [Bz * Uz];

// -------- monotonic grid barrier --------
__device__ unsigned g_ctr  = 0;
__device__ unsigned g_base = 0;

__global__ void set_base() { g_base = g_ctr; }

__device__ __forceinline__ void gsync(unsigned tgt) {
    __syncthreads();
    if (threadIdx.x == 0) {
        unsigned old;
        asm volatile("atom.add.release.gpu.global.u32 %0, [%1], 1;"
                     : "=r"(old) : "l"(&g_ctr) : "memory");
        unsigned v;
        for (;;) {
            asm volatile("ld.acquire.gpu.global.u32 %0, [%1];"
                         : "=r"(v) : "l"(&g_ctr) : "memory");
            if ((int)(v - tgt) >= 0) break;
            __nanosleep(40);
        }
    }
    __syncthreads();
}

// -------- f32x2 helpers --------
__device__ __forceinline__ void fma2(ull& d, ull a, ull b) {
    asm("fma.rn.f32x2 %0, %1, %2, %0;" : "+l"(d) : "l"(a), "l"(b));
}
__device__ __forceinline__ void add2(ull& d, ull a) {
    asm("add.rn.f32x2 %0, %1, %0;" : "+l"(d) : "l"(a));
}
__device__ __forceinline__ float hadd2(ull v) {
    float2 r; asm("mov.b64 {%0,%1}, %2;" : "=f"(r.x), "=f"(r.y) : "l"(v));
    return r.x + r.y;
}

// -------- mbarrier / bulk-async helpers --------
__device__ __forceinline__ void mbar_init(uint32_t mbar) {
    asm volatile("mbarrier.init.shared.b64 [%0], %1;" :: "r"(mbar), "r"(1) : "memory");
}
__device__ __forceinline__ void mbar_expect(uint32_t mbar, uint32_t bytes) {
    asm volatile("mbarrier.arrive.expect_tx.shared.b64 _, [%0], %1;"
                 :: "r"(mbar), "r"(bytes) : "memory");
}
__device__ __forceinline__ void bulk_g2s(uint32_t dst, const void* src,
                                         uint32_t bytes, uint32_t mbar) {
    asm volatile("cp.async.bulk.shared::cta.global.mbarrier::complete_tx::bytes "
                 "[%0], [%1], %2, [%3];"
                 :: "r"(dst), "l"(src), "r"(bytes), "r"(mbar) : "memory");
}
__device__ __forceinline__ void mbar_wait(uint32_t mbar, uint32_t parity) {
    asm volatile(
        "{\n\t.reg .pred P;\n"
        "W_%=:\n\t"
        "mbarrier.try_wait.parity.acquire.cta.shared::cta.b64 P, [%0], %1, 0x989680;\n\t"
        "@P bra D_%=;\n\t"
        "bra W_%=;\n"
        "D_%=:\n\t}"
        :: "r"(mbar), "r"(parity) : "memory");
}
__device__ __forceinline__ void fence_async() {
    asm volatile("fence.proxy.async;" ::: "memory");
}

// ------------------------------------------------------------------
// Round-2 GEMM verbatim (scalar FFMA, 2 blocks/SM, 58% fma pipe).
__global__ __launch_bounds__(256) void sgemm_bias(
    const float* __restrict__ Abase, const int* __restrict__ xidx,
    const float* __restrict__ W, const float* __restrict__ bias,
    float* __restrict__ C, int M, int N, int K)
{
    __shared__ float As[8][128];
    __shared__ float Bs[8][128];

    int tid = threadIdx.x;
    int ty = tid >> 4;
    int tx = tid & 15;
    int rowBase = blockIdx.y * 128;
    int colBase = blockIdx.x * 128;

    int arow  = tid >> 1;
    int acol4 = (tid & 1) * 4;
    int am = rowBase + arow;
    const float* arowptr;
    if (xidx) arowptr = Abase + (size_t)xidx[am] * K;
    else      arowptr = Abase + (size_t)am * K;

    int brow  = tid >> 5;
    int bcol4 = (tid & 31) * 4;

    float acc[8][8];
#pragma unroll
    for (int i = 0; i < 8; i++)
#pragma unroll
        for (int j = 0; j < 8; j++) acc[i][j] = 0.f;

    for (int k0 = 0; k0 < K; k0 += 8) {
        float4 av = *(const float4*)&arowptr[k0 + acol4];
        As[acol4 + 0][arow] = av.x;
        As[acol4 + 1][arow] = av.y;
        As[acol4 + 2][arow] = av.z;
        As[acol4 + 3][arow] = av.w;

        float4 bv = *(const float4*)&W[(size_t)(k0 + brow) * N + colBase + bcol4];
        *(float4*)&Bs[brow][bcol4] = bv;

        __syncthreads();
#pragma unroll
        for (int kk = 0; kk < 8; kk++) {
            float4 a0 = *(const float4*)&As[kk][ty * 8];
            float4 a1 = *(const float4*)&As[kk][ty * 8 + 4];
            float4 b0 = *(const float4*)&Bs[kk][tx * 8];
            float4 b1 = *(const float4*)&Bs[kk][tx * 8 + 4];
            float ar[8] = {a0.x,a0.y,a0.z,a0.w,a1.x,a1.y,a1.z,a1.w};
            float br[8] = {b0.x,b0.y,b0.z,b0.w,b1.x,b1.y,b1.z,b1.w};
#pragma unroll
            for (int i = 0; i < 8; i++)
#pragma unroll
                for (int j = 0; j < 8; j++)
                    acc[i][j] = fmaf(ar[i], br[j], acc[i][j]);
        }
        __syncthreads();
    }

    int col0 = colBase + tx * 8;
    float4 bia0 = *(const float4*)&bias[col0];
    float4 bia1 = *(const float4*)&bias[col0 + 4];
#pragma unroll
    for (int i = 0; i < 8; i++) {
        int row = rowBase + ty * 8 + i;
        float4 v0, v1;
        v0.x = acc[i][0] + bia0.x; v0.y = acc[i][1] + bia0.y;
        v0.z = acc[i][2] + bia0.z; v0.w = acc[i][3] + bia0.w;
        v1.x = acc[i][4] + bia1.x; v1.y = acc[i][5] + bia1.y;
        v1.z = acc[i][6] + bia1.z; v1.w = acc[i][7] + bia1.w;
        *(float4*)&C[(size_t)row * N + col0]     = v0;
        *(float4*)&C[(size_t)row * N + col0 + 4] = v1;
    }
}

// ------------------------------------------------------------------
// Persistent GRU scan. 128 blocks x 512 threads, 1 block/SM.
// Staging: cp.async.bulk of the whole padded h/a tile (131584 B) per phase.
// Phase1 threads: k8=tid>>6, bg=(tid>>3)&7, jj=tid&7. Tile: rows {bg+8d},
//   cols {2jj,2jj+1} of 16, k-range k8*128. 8-way k-split -> SMEM reduction.
// Phase2 threads: kc=tid>>5, bg=(tid>>2)&7, jj=tid&3. Tile: rows {bg+8d},
//   cols {2jj,2jj+1} of 8, k-range kc*64. 16-way split.
#define SWG_BYTES 65664
#define SWC_BYTES 32896
#define SH_OFF    (SWG_BYTES + SWC_BYTES)        // 98560
#define MBAR_OFF  (SH_OFF + BULKB)               // 230144
#define SMEM_BYTES (MBAR_OFF + 16)               // 230160

__global__ __launch_bounds__(NTHR) void gru_scan(
    const float* __restrict__ Wgh,   // [1024][2048]
    const float* __restrict__ Wch,   // [1024][1024]
    const float* __restrict__ Xg,    // [16384][2048]
    const float* __restrict__ Xc,    // [16384][1024]
    const float* __restrict__ h0,
    float* __restrict__ y,
    float* __restrict__ s_out)
{
    extern __shared__ char smraw[];
    char*  swg = smraw;
    char*  swc = smraw + SWG_BYTES;
    float* sh  = (float*)(smraw + SH_OFF);
    ull*   sred = (ull*)sh;                       // 32KB partial planes (overlay)

    const int tid = threadIdx.x;
    const int blk = blockIdx.x;
    const int jg0 = blk * 16;
    const int jc0 = blk * 8;
    const bool is_r = (jg0 < Uz);

    const uint32_t sh_s  = (uint32_t)__cvta_generic_to_shared(sh);
    const uint32_t mbar  = (uint32_t)__cvta_generic_to_shared(smraw + MBAR_OFF);

    // phase-1 mapping
    const int k8 = tid >> 6;
    const int bg1 = (tid >> 3) & 7;
    const int jj1 = tid & 7;
    // phase-2 mapping
    const int kc = tid >> 5;
    const int bg2 = (tid >> 2) & 7;
    const int jj2 = tid & 3;
    // epilogue mappings
    const int e1b = tid >> 4, e1j = tid & 15;          // phase1: 512 outputs
    const int e2b = tid >> 3, e2j = tid & 7;           // phase2: 256 outputs

    unsigned base = 0, nb = 0;
    if (tid == 0) base = g_base;

    if (tid == 0) mbar_init(mbar);
    unsigned parity = 0;

    // ---- preload W slices, transposed (once per layer) ----
    for (int i = tid; i < 4096; i += NTHR) {
        int k = i >> 2, c4 = (i & 3) * 4;
        float4 v = *(const float4*)&Wgh[(size_t)k * U2 + jg0 + c4];
        float vv[4] = {v.x, v.y, v.z, v.w};
#pragma unroll
        for (int d = 0; d < 4; d++) {
            int c = c4 + d;
            *(float*)(swg + (c >> 1) * 8208 + (c & 1) * 4096 + k * 4) = vv[d];
        }
    }
    for (int i = tid; i < 2048; i += NTHR) {
        int k = i >> 1, cb = (i & 1) * 4;
        float4 v = *(const float4*)&Wch[(size_t)k * Uz + jc0 + cb];
        float vv[4] = {v.x, v.y, v.z, v.w};
#pragma unroll
        for (int d = 0; d < 4; d++)
            *(float*)(swc + (cb + d) * 4112 + k * 4) = vv[d];
    }
    // init h (padded layout)
    for (int i = blk * NTHR + tid; i < Bz * Uz; i += NBLK * NTHR) {
        int b = i >> 10, u = i & 1023;
        __stcg(&g_h[b * PITCH + u], h0[i]);
    }
    nb++; gsync(base + nb * NBLK);

    for (int t = 0; t < Sz; t++) {
        // ================= phase 1: gates =================
        if (tid == 0) {
            fence_async();
            mbar_expect(mbar, BULKB);
            bulk_g2s(sh_s, g_h, BULKB, mbar);
        }
        // prefetch epilogue operands while bulk is in flight
        int m1 = e1b * Sz + t;
        float xg_pf = __ldcg(&Xg[(size_t)m1 * U2 + jg0 + e1j]);
        float h_pf = 0.f;
        if (is_r) h_pf = __ldcg(&g_h[e1b * PITCH + jg0 + e1j]);

        mbar_wait(mbar, parity); parity ^= 1;

        ull a00 = 0, a01 = 0, a10 = 0, a11 = 0, a20 = 0, a21 = 0, a30 = 0, a31 = 0;
        {
            const ulonglong2* h0p = (const ulonglong2*)(sh + (bg1 +  0) * PITCH + k8 * 128);
            const ulonglong2* h1p = (const ulonglong2*)(sh + (bg1 +  8) * PITCH + k8 * 128);
            const ulonglong2* h2p = (const ulonglong2*)(sh + (bg1 + 16) * PITCH + k8 * 128);
            const ulonglong2* h3p = (const ulonglong2*)(sh + (bg1 + 24) * PITCH + k8 * 128);
            const ulonglong2* w0p = (const ulonglong2*)(swg + jj1 * 8208 + k8 * 512);
            const ulonglong2* w1p = (const ulonglong2*)(swg + jj1 * 8208 + 4096 + k8 * 512);
#pragma unroll 4
            for (int i = 0; i < 32; i++) {
                ulonglong2 w0 = w0p[i], w1 = w1p[i];
                ulonglong2 hv;
                hv = h0p[i];
                fma2(a00, hv.x, w0.x); fma2(a00, hv.y, w0.y);
                fma2(a01, hv.x, w1.x); fma2(a01, hv.y, w1.y);
                hv = h1p[i];
                fma2(a10, hv.x, w0.x); fma2(a10, hv.y, w0.y);
                fma2(a11, hv.x, w1.x); fma2(a11, hv.y, w1.y);
                hv = h2p[i];
                fma2(a20, hv.x, w0.x); fma2(a20, hv.y, w0.y);
                fma2(a21, hv.x, w1.x); fma2(a21, hv.y, w1.y);
                hv = h3p[i];
                fma2(a30, hv.x, w0.x); fma2(a30, hv.y, w0.y);
                fma2(a31, hv.x, w1.x); fma2(a31, hv.y, w1.y);
            }
        }
        __syncthreads();   // everyone done reading sh before partial overlay
        {
            int ib = k8 * 512 + jj1 * 2;
            *(ulonglong2*)&sred[ib + (bg1 +  0) * 16] = make_ulonglong2(a00, a01);
            *(ulonglong2*)&sred[ib + (bg1 +  8) * 16] = make_ulonglong2(a10, a11);
            *(ulonglong2*)&sred[ib + (bg1 + 16) * 16] = make_ulonglong2(a20, a21);
            *(ulonglong2*)&sred[ib + (bg1 + 24) * 16] = make_ulonglong2(a30, a31);
        }
        __syncthreads();
        {
            ull s = sred[tid];
#pragma unroll
            for (int p = 1; p < 8; p++) add2(s, sred[p * 512 + tid]);
            float v = 1.f / (1.f + expf(-(xg_pf + hadd2(s))));
            if (is_r) __stcg(&g_a[e1b * PITCH + jg0 + e1j], v * h_pf);
            else      __stcg(&g_u[e1b * Uz + jg0 - Uz + e1j], v);
        }
        nb++; gsync(base + nb * NBLK);

        // ================= phase 2: candidate + update =================
        if (tid == 0) {
            fence_async();
            mbar_expect(mbar, BULKB);
            bulk_g2s(sh_s, g_a, BULKB, mbar);
        }
        int m2 = e2b * Sz + t;
        float xc_pf = 0.f, u_pf = 0.f, ho_pf = 0.f;
        if (tid < 256) {
            xc_pf = __ldcg(&Xc[(size_t)m2 * Uz + jc0 + e2j]);
            u_pf  = __ldcg(&g_u[e2b * Uz + jc0 + e2j]);
            ho_pf = __ldcg(&g_h[e2b * PITCH + jc0 + e2j]);
        }

        mbar_wait(mbar, parity); parity ^= 1;

        ull c00 = 0, c01 = 0, c10 = 0, c11 = 0, c20 = 0, c21 = 0, c30 = 0, c31 = 0;
        {
            const ulonglong2* a0p = (const ulonglong2*)(sh + (bg2 +  0) * PITCH + kc * 64);
            const ulonglong2* a1p = (const ulonglong2*)(sh + (bg2 +  8) * PITCH + kc * 64);
            const ulonglong2* a2p = (const ulonglong2*)(sh + (bg2 + 16) * PITCH + kc * 64);
            const ulonglong2* a3p = (const ulonglong2*)(sh + (bg2 + 24) * PITCH + kc * 64);
            const ulonglong2* wAp = (const ulonglong2*)(swc + (jj2 * 2) * 4112 + kc * 256);
            const ulonglong2* wBp = (const ulonglong2*)(swc + (jj2 * 2 + 1) * 4112 + kc * 256);
#pragma unroll 4
            for (int i = 0; i < 16; i++) {
                ulonglong2 wA = wAp[i], wB = wBp[i];
                ulonglong2 av;
                av = a0p[i];
                fma2(c00, av.x, wA.x); fma2(c00, av.y, wA.y);
                fma2(c01, av.x, wB.x); fma2(c01, av.y, wB.y);
                av = a1p[i];
                fma2(c10, av.x, wA.x); fma2(c10, av.y, wA.y);
                fma2(c11, av.x, wB.x); fma2(c11, av.y, wB.y);
                av = a2p[i];
                fma2(c20, av.x, wA.x); fma2(c20, av.y, wA.y);
                fma2(c21, av.x, wB.x); fma2(c21, av.y, wB.y);
                av = a3p[i];
                fma2(c30, av.x, wA.x); fma2(c30, av.y, wA.y);
                fma2(c31, av.x, wB.x); fma2(c31, av.y, wB.y);
            }
        }
        __syncthreads();
        {
            int ib = kc * 256 + jj2 * 2;
            *(ulonglong2*)&sred[ib + (bg2 +  0) * 8] = make_ulonglong2(c00, c01);
            *(ulonglong2*)&sred[ib + (bg2 +  8) * 8] = make_ulonglong2(c10, c11);
            *(ulonglong2*)&sred[ib + (bg2 + 16) * 8] = make_ulonglong2(c20, c21);
            *(ulonglong2*)&sred[ib + (bg2 + 24) * 8] = make_ulonglong2(c30, c31);
        }
        __syncthreads();
        if (tid < 256) {
            ull s = sred[tid];
#pragma unroll
            for (int p = 1; p < 16; p++) add2(s, sred[p * 256 + tid]);
            float c  = tanhf(xc_pf + hadd2(s));
            float hn = u_pf * ho_pf + (1.f - u_pf) * c;
            __stcg(&g_h[e2b * PITCH + jc0 + e2j], hn);
            y[(size_t)m2 * Uz + jc0 + e2j] = hn;
        }
        nb++; gsync(base + nb * NBLK);
    }

    // ---- write final state (de-pad) ----
    for (int i = blk * NTHR + tid; i < Bz * Uz; i += NBLK * NTHR) {
        int b = i >> 10, u = i & 1023;
        s_out[i] = __ldcg(&g_h[b * PITCH + u]);
    }
}

// ------------------------------------------------------------------
extern "C" void kernel_launch(void* const* d_in, const int* in_sizes, int n_in,
                              void* d_out, int out_size)
{
    const int*   x    = (const int*)  d_in[0];
    const float* h0_0 = (const float*)d_in[1];
    const float* h0_1 = (const float*)d_in[2];
    const float* emb  = (const float*)d_in[3];
    const float* Wg0  = (const float*)d_in[4];
    const float* bg0  = (const float*)d_in[5];
    const float* Wc0  = (const float*)d_in[6];
    const float* bc0  = (const float*)d_in[7];
    const float* Wg1  = (const float*)d_in[8];
    const float* bg1  = (const float*)d_in[9];
    const float* Wc1  = (const float*)d_in[10];
    const float* bc1  = (const float*)d_in[11];
    float* out = (float*)d_out;

    float *Xg, *Xc, *y0;
    cudaGetSymbolAddress((void**)&Xg, g_Xg);
    cudaGetSymbolAddress((void**)&Xc, g_Xc);
    cudaGetSymbolAddress((void**)&y0, g_y0);

    static int smem_set = 0;
    if (!smem_set) {
        cudaFuncSetAttribute(gru_scan, cudaFuncAttributeMaxDynamicSharedMemorySize, SMEM_BYTES);
        smem_set = 1;
    }

    float* s0_out = out + (size_t)BSz * Uz;
    float* s1_out = s0_out + Bz * Uz;

    // ---------- layer 0 ----------
    sgemm_bias<<<dim3(U2 / 128, BSz / 128), 256>>>(emb, x, Wg0, bg0, Xg, BSz, U2, Ez);
    sgemm_bias<<<dim3(Uz / 128, BSz / 128), 256>>>(emb, x, Wc0, bc0, Xc, BSz, Uz, Ez);
    set_base<<<1, 1>>>();
    gru_scan<<<NBLK, NTHR, SMEM_BYTES>>>(
        Wg0 + (size_t)Ez * U2, Wc0 + (size_t)Ez * Uz, Xg, Xc, h0_0, y0, s0_out);

    // ---------- layer 1 ----------
    sgemm_bias<<<dim3(U2 / 128, BSz / 128), 256>>>(y0, nullptr, Wg1, bg1, Xg, BSz, U2, Uz);
    sgemm_bias<<<dim3(Uz / 128, BSz / 128), 256>>>(y0, nullptr, Wc1, bc1, Xc, BSz, Uz, Uz);
    set_base<<<1, 1>>>();
    gru_scan<<<NBLK, NTHR, SMEM_BYTES>>>(
        Wg1 + (size_t)Uz * U2, Wc1 + (size_t)Uz * Uz, Xg, Xc, h0_1, out, s1_out);
}